// round 7
// baseline (speedup 1.0000x reference)
#include <cuda_runtime.h>
#include <cuda_fp16.h>
#include <mma.h>
#include <cstdint>

using namespace nvcuda;

#define NN 100000
#define NE 600000
#define C 128
#define OC 64
#define NREL 3
#define HLD 136   // fp16 tile stride (halves)
#define FLD 132   // f32 tile stride (floats)

// ---------------- scratch (static device globals) ---------------------------
__device__ float g_agg[(size_t)NREL * NN * C];
__device__ float g_cnt[NREL * NN];
__device__ float g_t[(size_t)NN * OC];
__device__ float g_aggF[(size_t)NN * OC];
__device__ float g_po[(size_t)NN * OC];
__device__ float g_bias_rep[NREL * 16 * C];   // bl replicated over 16 rows
__device__ float g_bias_rep_f[16 * C];        // [0|blf] replicated over 16 rows

__device__ __forceinline__ void red_add_v4(float* p, float4 v) {
    asm volatile("red.global.add.v4.f32 [%0], {%1, %2, %3, %4};"
                 :: "l"(p), "f"(v.x), "f"(v.y), "f"(v.z), "f"(v.w) : "memory");
}

// ---------------- kernel P: replicate biases --------------------------------
__global__ void k_prep(const float* __restrict__ bl, const float* __restrict__ blf) {
    int tid = threadIdx.x;
    for (int i = tid; i < NREL * 16 * C; i += 256) {
        int r = i / (16 * C);
        int col = i & (C - 1);
        g_bias_rep[i] = bl[r * C + col];
    }
    for (int i = tid; i < 16 * C; i += 256) {
        int col = i & (C - 1);
        g_bias_rep_f[i] = (col < OC) ? 0.f : blf[col - OC];
    }
}

// ---------------- kernel 1: scatter x, 8 edges per warp ---------------------
__global__ __launch_bounds__(512)
void k_scatter_x(const float* __restrict__ x,
                 const int* __restrict__ ei0,
                 const int* __restrict__ ei1,
                 const int* __restrict__ ei2) {
    int r = blockIdx.y;
    const int* ei = (r == 0) ? ei0 : (r == 1) ? ei1 : ei2;
    int w = (blockIdx.x * blockDim.x + threadIdx.x) >> 5;
    int lane = threadIdx.x & 31;
    int e0 = w * 8;
    if (e0 >= NE) return;
    int s[8], d[8];
    bool ok[8];
#pragma unroll
    for (int e = 0; e < 8; e++) {
        s[e] = ei[e0 + e];
        d[e] = ei[NE + e0 + e];
        ok[e] = ((unsigned)s[e] < NN) && ((unsigned)d[e] < NN);
    }
    float4 v[8];
#pragma unroll
    for (int e = 0; e < 8; e++)
        if (ok[e])
            v[e] = *reinterpret_cast<const float4*>(x + (size_t)s[e] * C + lane * 4);
#pragma unroll
    for (int e = 0; e < 8; e++)
        if (ok[e])
            red_add_v4(g_agg + (size_t)r * NN * C + (size_t)d[e] * C + lane * 4, v[e]);
    if (lane < 8 && ok[lane])
        atomicAdd(&g_cnt[r * NN + d[lane]], 1.f);
}

// ---------------- fused fp16 WMMA GEMM kernel (512 thr, 16 warps 4x4) -------
__global__ __launch_bounds__(512, 1)
void k_gemm_fused(const float* __restrict__ x,  const float* __restrict__ Wl,
                  const float* __restrict__ Wr, const float* __restrict__ Wlf,
                  const float* __restrict__ Wrf) {
    extern __shared__ char smraw[];
    // phase-1 layout: X, A, Wl, Wr all [128][HLD] fp16 (34816B each)
    __half* X_s  = reinterpret_cast<__half*>(smraw);
    __half* A_s  = X_s + 128 * HLD;
    __half* Wl_s = A_s + 128 * HLD;
    __half* Wr_s = Wl_s + 128 * HLD;
    // phase-2 aliases
    float*  H32  = reinterpret_cast<float*>(smraw);              // [128][FLD] over X+A
    __half* Hh   = Wl_s;                                         // [128][HLD] over Wl
    __half* Wf_s = Wr_s;                                         // [128][HLD] over Wr
    float*  Df   = reinterpret_cast<float*>(smraw);              // [128][FLD] over X+A

    int tid  = threadIdx.x;
    int wid  = tid >> 5;
    int node0 = blockIdx.x * 128;
    int wm = (wid >> 2) * 32;   // warp row offset
    int wn = (wid & 3) * 32;    // warp col offset

    // stage X tile (fp16)
    for (int it = tid; it < 128 * 32; it += 512) {
        int row = it >> 5, c4 = it & 31;
        int node = node0 + row;
        float4 v = make_float4(0.f, 0.f, 0.f, 0.f);
        if (node < NN)
            v = *reinterpret_cast<const float4*>(x + (size_t)node * C + c4 * 4);
        __half2* dp = reinterpret_cast<__half2*>(X_s + row * HLD + c4 * 4);
        dp[0] = __floats2half2_rn(v.x, v.y);
        dp[1] = __floats2half2_rn(v.z, v.w);
    }

    wmma::fragment<wmma::accumulator, 16, 16, 16, float> hfrag[2][2];
#pragma unroll
    for (int i = 0; i < 2; i++)
#pragma unroll
        for (int j = 0; j < 2; j++) wmma::fill_fragment(hfrag[i][j], 0.f);
    const float inv3 = 1.f / 3.f;

    for (int r = 0; r < NREL; r++) {
        __syncthreads();  // prior MMAs done reading A_s/W (X staged, iter 0)
        // stage mean-agg tile (fp16)
        {
            const float* aggr = g_agg + (size_t)r * NN * C;
            const float* cntr = g_cnt + r * NN;
            for (int it = tid; it < 128 * 32; it += 512) {
                int row = it >> 5, c4 = it & 31;
                int node = node0 + row;
                float4 v = make_float4(0.f, 0.f, 0.f, 0.f);
                if (node < NN) {
                    float inv = 1.f / fmaxf(cntr[node], 1.f);
                    float4 a = *reinterpret_cast<const float4*>(
                        aggr + (size_t)node * C + c4 * 4);
                    v.x = a.x * inv; v.y = a.y * inv;
                    v.z = a.z * inv; v.w = a.w * inv;
                }
                __half2* dp = reinterpret_cast<__half2*>(A_s + row * HLD + c4 * 4);
                dp[0] = __floats2half2_rn(v.x, v.y);
                dp[1] = __floats2half2_rn(v.z, v.w);
            }
        }
        // stage full Wl[r], Wr[r] (128 k rows x 128 n cols, fp16)
        for (int it = tid; it < 128 * 32; it += 512) {
            int kk = it >> 5, c4 = it & 31;
            size_t off = (size_t)r * C * C + (size_t)kk * C + c4 * 4;
            float4 vl = *reinterpret_cast<const float4*>(Wl + off);
            float4 vr = *reinterpret_cast<const float4*>(Wr + off);
            __half2* dl = reinterpret_cast<__half2*>(Wl_s + kk * HLD + c4 * 4);
            dl[0] = __floats2half2_rn(vl.x, vl.y);
            dl[1] = __floats2half2_rn(vl.z, vl.w);
            __half2* dr = reinterpret_cast<__half2*>(Wr_s + kk * HLD + c4 * 4);
            dr[0] = __floats2half2_rn(vr.x, vr.y);
            dr[1] = __floats2half2_rn(vr.z, vr.w);
        }

        // acc = bias (fragment load from replicated global bias tile)
        wmma::fragment<wmma::accumulator, 16, 16, 16, float> acc[2][2];
#pragma unroll
        for (int i = 0; i < 2; i++)
#pragma unroll
            for (int j = 0; j < 2; j++)
                wmma::load_matrix_sync(acc[i][j],
                    g_bias_rep + r * 16 * C + wn + j * 16, C, wmma::mem_row_major);
        __syncthreads();

#pragma unroll
        for (int ks = 0; ks < 8; ks++) {
            int k = ks * 16;
            wmma::fragment<wmma::matrix_a, 16, 16, 16, __half,
                           wmma::row_major> af[2], xf[2];
            wmma::fragment<wmma::matrix_b, 16, 16, 16, __half,
                           wmma::row_major> lf[2], rf[2];
#pragma unroll
            for (int i = 0; i < 2; i++) {
                wmma::load_matrix_sync(af[i], A_s + (wm + i * 16) * HLD + k, HLD);
                wmma::load_matrix_sync(xf[i], X_s + (wm + i * 16) * HLD + k, HLD);
            }
#pragma unroll
            for (int j = 0; j < 2; j++) {
                wmma::load_matrix_sync(lf[j], Wl_s + k * HLD + wn + j * 16, HLD);
                wmma::load_matrix_sync(rf[j], Wr_s + k * HLD + wn + j * 16, HLD);
            }
#pragma unroll
            for (int i = 0; i < 2; i++)
#pragma unroll
                for (int j = 0; j < 2; j++) {
                    wmma::mma_sync(acc[i][j], af[i], lf[j], acc[i][j]);
                    wmma::mma_sync(acc[i][j], xf[i], rf[j], acc[i][j]);
                }
        }

        // h += relu(acc)/3  (elementwise, identical fragment layouts)
#pragma unroll
        for (int i = 0; i < 2; i++)
#pragma unroll
            for (int j = 0; j < 2; j++)
#pragma unroll
                for (int t = 0; t < hfrag[i][j].num_elements; t++)
                    hfrag[i][j].x[t] += fmaxf(acc[i][j].x[t], 0.f) * inv3;
    }

    // ---------------- final GEMM: D_f = h @ [Wlf | Wrf] ---------------------
    __syncthreads();  // last MMAs done reading X_s/A_s/W
    // store h (f32) into H32 (over X+A)
#pragma unroll
    for (int i = 0; i < 2; i++)
#pragma unroll
        for (int j = 0; j < 2; j++)
            wmma::store_matrix_sync(H32 + (wm + i * 16) * FLD + wn + j * 16,
                                    hfrag[i][j], FLD, wmma::mem_row_major);
    __syncthreads();
    // convert H32 -> Hh (fp16, over Wl_s); stage Wf (fp16, over Wr_s)
    for (int it = tid; it < 128 * 64; it += 512) {
        int row = it >> 6, c2 = it & 63;
        float2 v = *reinterpret_cast<const float2*>(H32 + row * FLD + c2 * 2);
        *reinterpret_cast<__half2*>(Hh + row * HLD + c2 * 2) =
            __floats2half2_rn(v.x, v.y);
    }
    for (int it = tid; it < 128 * 32; it += 512) {
        int k = it >> 5, c4 = it & 31;
        int col = c4 * 4;
        float4 v;
        if (col < OC)
            v = *reinterpret_cast<const float4*>(Wlf + (size_t)k * OC + col);
        else
            v = *reinterpret_cast<const float4*>(Wrf + (size_t)k * OC + (col - OC));
        __half2* dp = reinterpret_cast<__half2*>(Wf_s + k * HLD + col);
        dp[0] = __floats2half2_rn(v.x, v.y);
        dp[1] = __floats2half2_rn(v.z, v.w);
    }
    __syncthreads();

    {
        wmma::fragment<wmma::accumulator, 16, 16, 16, float> acc2[2][2];
#pragma unroll
        for (int i = 0; i < 2; i++)
#pragma unroll
            for (int j = 0; j < 2; j++)
                wmma::load_matrix_sync(acc2[i][j],
                    g_bias_rep_f + wn + j * 16, C, wmma::mem_row_major);

#pragma unroll
        for (int ks = 0; ks < 8; ks++) {
            int k = ks * 16;
            wmma::fragment<wmma::matrix_a, 16, 16, 16, __half,
                           wmma::row_major> hf[2];
            wmma::fragment<wmma::matrix_b, 16, 16, 16, __half,
                           wmma::row_major> wf[2];
#pragma unroll
            for (int i = 0; i < 2; i++)
                wmma::load_matrix_sync(hf[i], Hh + (wm + i * 16) * HLD + k, HLD);
#pragma unroll
            for (int j = 0; j < 2; j++)
                wmma::load_matrix_sync(wf[j], Wf_s + k * HLD + wn + j * 16, HLD);
#pragma unroll
            for (int i = 0; i < 2; i++)
#pragma unroll
                for (int j = 0; j < 2; j++)
                    wmma::mma_sync(acc2[i][j], hf[i], wf[j], acc2[i][j]);
        }
        __syncthreads();  // all warps done reading Hh/Wf (and H32 region)
#pragma unroll
        for (int i = 0; i < 2; i++)
#pragma unroll
            for (int j = 0; j < 2; j++)
                wmma::store_matrix_sync(Df + (wm + i * 16) * FLD + wn + j * 16,
                                        acc2[i][j], FLD, wmma::mem_row_major);
        __syncthreads();
    }

    // epilogue: t (cols 0..63), po (cols 64..127); zero this tile's aggF slice
    {
        int row = tid >> 2;
        int ec  = (tid & 3) * 32;
        int node = node0 + row;
        if (node < NN) {
            if (ec < OC) {
                float* tp = g_t + (size_t)node * OC + ec;
                float* zp = g_aggF + (size_t)node * OC + ec;
#pragma unroll
                for (int q = 0; q < 8; q++) {
                    *reinterpret_cast<float4*>(tp + q * 4) =
                        *reinterpret_cast<const float4*>(Df + row * FLD + ec + q * 4);
                    *reinterpret_cast<float4*>(zp + q * 4) =
                        make_float4(0.f, 0.f, 0.f, 0.f);
                }
            } else {
                float* pp = g_po + (size_t)node * OC + (ec - OC);
                float* zp = g_aggF + (size_t)node * OC + (ec - OC);
#pragma unroll
                for (int q = 0; q < 8; q++) {
                    *reinterpret_cast<float4*>(pp + q * 4) =
                        *reinterpret_cast<const float4*>(Df + row * FLD + ec + q * 4);
                    // note: both halves zero the same 64-col aggF row? no:
                    // ec-OC spans 0..63 here and ec spans 0..63 above -> disjoint
                    // halves handled by (tid&3): 0,1 -> cols 0..63 ; 2,3 -> 0..63.
                    // Writing twice is benign (same zero value).
                    *reinterpret_cast<float4*>(zp + q * 4) =
                        make_float4(0.f, 0.f, 0.f, 0.f);
                }
            }
        }
    }
}

// ---------------- kernel 4: scatter t, 8 edges per half-warp ----------------
__global__ __launch_bounds__(512)
void k_scatter_t(const int* __restrict__ ei) {
    int hw = (blockIdx.x * blockDim.x + threadIdx.x) >> 4;
    int lane = threadIdx.x & 15;
    int e0 = hw * 8;
    if (e0 >= NE) return;
    int s[8], d[8];
    bool ok[8];
#pragma unroll
    for (int e = 0; e < 8; e++) {
        s[e] = ei[e0 + e];
        d[e] = ei[NE + e0 + e];
        ok[e] = ((unsigned)s[e] < NN) && ((unsigned)d[e] < NN);
    }
    float4 v[8];
#pragma unroll
    for (int e = 0; e < 8; e++)
        if (ok[e])
            v[e] = *reinterpret_cast<const float4*>(g_t + (size_t)s[e] * OC + lane * 4);
#pragma unroll
    for (int e = 0; e < 8; e++)
        if (ok[e])
            red_add_v4(g_aggF + (size_t)d[e] * OC + lane * 4, v[e]);
}

// ---------------- kernel 5: out = aggF / max(cnt0,1) + po -------------------
__global__ void k_final(float* __restrict__ out) {
    int i = blockIdx.x * blockDim.x + threadIdx.x;
    int stride = gridDim.x * blockDim.x;
    int n4 = NN * OC / 4;
    const float4* a4 = reinterpret_cast<const float4*>(g_aggF);
    const float4* p4 = reinterpret_cast<const float4*>(g_po);
    float4* o4 = reinterpret_cast<float4*>(out);
    for (int j = i; j < n4; j += stride) {
        int node = j / (OC / 4);
        float inv = 1.f / fmaxf(g_cnt[node], 1.f);
        float4 a = a4[j];
        float4 p = p4[j];
        o4[j] = make_float4(a.x * inv + p.x, a.y * inv + p.y,
                            a.z * inv + p.z, a.w * inv + p.w);
    }
}

// ---------------- launch ----------------------------------------------------
extern "C" void kernel_launch(void* const* d_in, const int* in_sizes, int n_in,
                              void* d_out, int out_size) {
    const float* x   = (const float*)d_in[0];
    const float* Wl  = (const float*)d_in[1];
    const float* bl  = (const float*)d_in[2];
    const float* Wr  = (const float*)d_in[3];
    const float* Wlf = (const float*)d_in[4];
    const float* blf = (const float*)d_in[5];
    const float* Wrf = (const float*)d_in[6];
    const int* ei0   = (const int*)d_in[7];
    const int* ei1   = (const int*)d_in[8];
    const int* ei2   = (const int*)d_in[9];
    float* out = (float*)d_out;

    void *pagg, *pcnt;
    cudaGetSymbolAddress(&pagg, g_agg);
    cudaGetSymbolAddress(&pcnt, g_cnt);
    cudaMemsetAsync(pagg, 0, (size_t)NREL * NN * C * sizeof(float), 0);
    cudaMemsetAsync(pcnt, 0, (size_t)NREL * NN * sizeof(float), 0);

    k_prep<<<1, 256>>>(bl, blf);

    // 8 edges per warp, 16 warps per 512-thr block, y = relation
    dim3 sgrid((NE / 8 + 15) / 16, 3);
    k_scatter_x<<<sgrid, 512>>>(x, ei0, ei1, ei2);

    const int SMEMF = 4 * 128 * HLD * 2;  // 139264
    cudaFuncSetAttribute(k_gemm_fused, cudaFuncAttributeMaxDynamicSharedMemorySize, SMEMF);
    int gb = (NN + 127) / 128;  // 782
    k_gemm_fused<<<gb, 512, SMEMF>>>(x, Wl, Wr, Wlf, Wrf);

    // 8 edges per half-warp, 32 half-warps per 512-thr block
    k_scatter_t<<<(NE / 8 + 31) / 32, 512>>>(ei0);
    k_final<<<2048, 256>>>(out);
}

// round 8
// speedup vs baseline: 1.0530x; 1.0530x over previous
#include <cuda_runtime.h>
#include <cuda_fp16.h>
#include <mma.h>
#include <cstdint>

using namespace nvcuda;

#define NN 100000
#define NE 600000
#define C 128
#define OC 64
#define NREL 3
#define HLD 136   // fp16 tile stride (halves)
#define FLD 132   // f32 tile stride (floats)

// ---------------- scratch (static device globals) ---------------------------
__device__ float g_agg[(size_t)NREL * NN * C];
__device__ float g_cnt[NREL * NN];
__device__ float g_t[(size_t)NN * OC];
__device__ float g_aggF[(size_t)NN * OC];
__device__ float g_po[(size_t)NN * OC];
__device__ float g_bias_rep[NREL * 16 * C];   // bl replicated over 16 rows
__device__ float g_bias_rep_f[16 * C];        // [0|blf] replicated over 16 rows

__device__ __forceinline__ void red_add_v4(float* p, float4 v) {
    asm volatile("red.global.add.v4.f32 [%0], {%1, %2, %3, %4};"
                 :: "l"(p), "f"(v.x), "f"(v.y), "f"(v.z), "f"(v.w) : "memory");
}

// ---------------- kernel P: replicate biases --------------------------------
__global__ void k_prep(const float* __restrict__ bl, const float* __restrict__ blf) {
    int tid = threadIdx.x;
    for (int i = tid; i < NREL * 16 * C; i += 256) {
        int r = i / (16 * C);
        int col = i & (C - 1);
        g_bias_rep[i] = bl[r * C + col];
    }
    for (int i = tid; i < 16 * C; i += 256) {
        int col = i & (C - 1);
        g_bias_rep_f[i] = (col < OC) ? 0.f : blf[col - OC];
    }
}

// ---------------- kernel 1: scatter x, 4 edges per warp (R6 config) ---------
__global__ void k_scatter_x(const float* __restrict__ x,
                            const int* __restrict__ ei0,
                            const int* __restrict__ ei1,
                            const int* __restrict__ ei2) {
    int r = blockIdx.y;
    const int* ei = (r == 0) ? ei0 : (r == 1) ? ei1 : ei2;
    int w = (blockIdx.x * blockDim.x + threadIdx.x) >> 5;
    int lane = threadIdx.x & 31;
    int e0 = w * 4;
    if (e0 >= NE) return;
    int s[4], d[4];
    bool ok[4];
#pragma unroll
    for (int e = 0; e < 4; e++) {
        s[e] = ei[e0 + e];
        d[e] = ei[NE + e0 + e];
        ok[e] = ((unsigned)s[e] < NN) && ((unsigned)d[e] < NN);
    }
    float4 v[4];
#pragma unroll
    for (int e = 0; e < 4; e++)
        if (ok[e])
            v[e] = *reinterpret_cast<const float4*>(x + (size_t)s[e] * C + lane * 4);
#pragma unroll
    for (int e = 0; e < 4; e++)
        if (ok[e])
            red_add_v4(g_agg + (size_t)r * NN * C + (size_t)d[e] * C + lane * 4, v[e]);
    if (lane < 4 && ok[lane])
        atomicAdd(&g_cnt[r * NN + d[lane]], 1.f);
}

// ---------------- fused fp16 WMMA GEMM kernel (512 thr, 16 warps 4x4) -------
__global__ __launch_bounds__(512, 1)
void k_gemm_fused(const float* __restrict__ x,  const float* __restrict__ Wl,
                  const float* __restrict__ Wr, const float* __restrict__ Wlf,
                  const float* __restrict__ Wrf) {
    extern __shared__ char smraw[];
    // phase-1 layout: X, A, Wl, Wr all [128][HLD] fp16 (34816B each)
    __half* X_s  = reinterpret_cast<__half*>(smraw);
    __half* A_s  = X_s + 128 * HLD;
    __half* Wl_s = A_s + 128 * HLD;
    __half* Wr_s = Wl_s + 128 * HLD;
    // phase-2 aliases
    float*  H32  = reinterpret_cast<float*>(smraw);              // [128][FLD] over X+A
    __half* Hh   = Wl_s;                                         // [128][HLD] over Wl
    __half* Wf_s = Wr_s;                                         // [128][HLD] over Wr
    float*  Df   = reinterpret_cast<float*>(smraw);              // [128][FLD] over X+A

    int tid  = threadIdx.x;
    int wid  = tid >> 5;
    int node0 = blockIdx.x * 128;
    int wm = (wid >> 2) * 32;   // warp row offset
    int wn = (wid & 3) * 32;    // warp col offset

    // stage X tile (fp16)
    for (int it = tid; it < 128 * 32; it += 512) {
        int row = it >> 5, c4 = it & 31;
        int node = node0 + row;
        float4 v = make_float4(0.f, 0.f, 0.f, 0.f);
        if (node < NN)
            v = *reinterpret_cast<const float4*>(x + (size_t)node * C + c4 * 4);
        __half2* dp = reinterpret_cast<__half2*>(X_s + row * HLD + c4 * 4);
        dp[0] = __floats2half2_rn(v.x, v.y);
        dp[1] = __floats2half2_rn(v.z, v.w);
    }

    wmma::fragment<wmma::accumulator, 16, 16, 16, float> hfrag[2][2];
#pragma unroll
    for (int i = 0; i < 2; i++)
#pragma unroll
        for (int j = 0; j < 2; j++) wmma::fill_fragment(hfrag[i][j], 0.f);
    const float inv3 = 1.f / 3.f;

    for (int r = 0; r < NREL; r++) {
        __syncthreads();  // prior MMAs done reading A_s/W (X staged, iter 0)
        // stage mean-agg tile (fp16)
        {
            const float* aggr = g_agg + (size_t)r * NN * C;
            const float* cntr = g_cnt + r * NN;
            for (int it = tid; it < 128 * 32; it += 512) {
                int row = it >> 5, c4 = it & 31;
                int node = node0 + row;
                float4 v = make_float4(0.f, 0.f, 0.f, 0.f);
                if (node < NN) {
                    float inv = 1.f / fmaxf(cntr[node], 1.f);
                    float4 a = *reinterpret_cast<const float4*>(
                        aggr + (size_t)node * C + c4 * 4);
                    v.x = a.x * inv; v.y = a.y * inv;
                    v.z = a.z * inv; v.w = a.w * inv;
                }
                __half2* dp = reinterpret_cast<__half2*>(A_s + row * HLD + c4 * 4);
                dp[0] = __floats2half2_rn(v.x, v.y);
                dp[1] = __floats2half2_rn(v.z, v.w);
            }
        }
        // stage full Wl[r], Wr[r] (128 k rows x 128 n cols, fp16)
        for (int it = tid; it < 128 * 32; it += 512) {
            int kk = it >> 5, c4 = it & 31;
            size_t off = (size_t)r * C * C + (size_t)kk * C + c4 * 4;
            float4 vl = *reinterpret_cast<const float4*>(Wl + off);
            float4 vr = *reinterpret_cast<const float4*>(Wr + off);
            __half2* dl = reinterpret_cast<__half2*>(Wl_s + kk * HLD + c4 * 4);
            dl[0] = __floats2half2_rn(vl.x, vl.y);
            dl[1] = __floats2half2_rn(vl.z, vl.w);
            __half2* dr = reinterpret_cast<__half2*>(Wr_s + kk * HLD + c4 * 4);
            dr[0] = __floats2half2_rn(vr.x, vr.y);
            dr[1] = __floats2half2_rn(vr.z, vr.w);
        }

        // acc = bias (fragment load from replicated global bias tile)
        wmma::fragment<wmma::accumulator, 16, 16, 16, float> acc[2][2];
#pragma unroll
        for (int i = 0; i < 2; i++)
#pragma unroll
            for (int j = 0; j < 2; j++)
                wmma::load_matrix_sync(acc[i][j],
                    g_bias_rep + r * 16 * C + wn + j * 16, C, wmma::mem_row_major);
        __syncthreads();

#pragma unroll
        for (int ks = 0; ks < 8; ks++) {
            int k = ks * 16;
            wmma::fragment<wmma::matrix_a, 16, 16, 16, __half,
                           wmma::row_major> af[2], xf[2];
            wmma::fragment<wmma::matrix_b, 16, 16, 16, __half,
                           wmma::row_major> lf[2], rf[2];
#pragma unroll
            for (int i = 0; i < 2; i++) {
                wmma::load_matrix_sync(af[i], A_s + (wm + i * 16) * HLD + k, HLD);
                wmma::load_matrix_sync(xf[i], X_s + (wm + i * 16) * HLD + k, HLD);
            }
#pragma unroll
            for (int j = 0; j < 2; j++) {
                wmma::load_matrix_sync(lf[j], Wl_s + k * HLD + wn + j * 16, HLD);
                wmma::load_matrix_sync(rf[j], Wr_s + k * HLD + wn + j * 16, HLD);
            }
#pragma unroll
            for (int i = 0; i < 2; i++)
#pragma unroll
                for (int j = 0; j < 2; j++) {
                    wmma::mma_sync(acc[i][j], af[i], lf[j], acc[i][j]);
                    wmma::mma_sync(acc[i][j], xf[i], rf[j], acc[i][j]);
                }
        }

        // h += relu(acc)/3  (elementwise, identical fragment layouts)
#pragma unroll
        for (int i = 0; i < 2; i++)
#pragma unroll
            for (int j = 0; j < 2; j++)
#pragma unroll
                for (int t = 0; t < hfrag[i][j].num_elements; t++)
                    hfrag[i][j].x[t] += fmaxf(acc[i][j].x[t], 0.f) * inv3;
    }

    // ---------------- final GEMM: D_f = h @ [Wlf | Wrf] ---------------------
    __syncthreads();  // last MMAs done reading X_s/A_s/W
    // store h (f32) into H32 (over X+A)
#pragma unroll
    for (int i = 0; i < 2; i++)
#pragma unroll
        for (int j = 0; j < 2; j++)
            wmma::store_matrix_sync(H32 + (wm + i * 16) * FLD + wn + j * 16,
                                    hfrag[i][j], FLD, wmma::mem_row_major);
    __syncthreads();
    // convert H32 -> Hh (fp16, over Wl_s); stage Wf (fp16, over Wr_s)
    for (int it = tid; it < 128 * 64; it += 512) {
        int row = it >> 6, c2 = it & 63;
        float2 v = *reinterpret_cast<const float2*>(H32 + row * FLD + c2 * 2);
        *reinterpret_cast<__half2*>(Hh + row * HLD + c2 * 2) =
            __floats2half2_rn(v.x, v.y);
    }
    for (int it = tid; it < 128 * 32; it += 512) {
        int k = it >> 5, c4 = it & 31;
        int col = c4 * 4;
        float4 v;
        if (col < OC)
            v = *reinterpret_cast<const float4*>(Wlf + (size_t)k * OC + col);
        else
            v = *reinterpret_cast<const float4*>(Wrf + (size_t)k * OC + (col - OC));
        __half2* dp = reinterpret_cast<__half2*>(Wf_s + k * HLD + col);
        dp[0] = __floats2half2_rn(v.x, v.y);
        dp[1] = __floats2half2_rn(v.z, v.w);
    }
    __syncthreads();

    {
        wmma::fragment<wmma::accumulator, 16, 16, 16, float> acc2[2][2];
#pragma unroll
        for (int i = 0; i < 2; i++)
#pragma unroll
            for (int j = 0; j < 2; j++)
                wmma::load_matrix_sync(acc2[i][j],
                    g_bias_rep_f + wn + j * 16, C, wmma::mem_row_major);

#pragma unroll
        for (int ks = 0; ks < 8; ks++) {
            int k = ks * 16;
            wmma::fragment<wmma::matrix_a, 16, 16, 16, __half,
                           wmma::row_major> hf[2];
            wmma::fragment<wmma::matrix_b, 16, 16, 16, __half,
                           wmma::row_major> wf[2];
#pragma unroll
            for (int i = 0; i < 2; i++)
                wmma::load_matrix_sync(hf[i], Hh + (wm + i * 16) * HLD + k, HLD);
#pragma unroll
            for (int j = 0; j < 2; j++)
                wmma::load_matrix_sync(wf[j], Wf_s + k * HLD + wn + j * 16, HLD);
#pragma unroll
            for (int i = 0; i < 2; i++)
#pragma unroll
                for (int j = 0; j < 2; j++)
                    wmma::mma_sync(acc2[i][j], hf[i], wf[j], acc2[i][j]);
        }
        __syncthreads();  // all warps done reading Hh/Wf
#pragma unroll
        for (int i = 0; i < 2; i++)
#pragma unroll
            for (int j = 0; j < 2; j++)
                wmma::store_matrix_sync(Df + (wm + i * 16) * FLD + wn + j * 16,
                                        acc2[i][j], FLD, wmma::mem_row_major);
        __syncthreads();
    }

    // epilogue: t (cols 0..63), po (cols 64..127); zero this tile's aggF slice
    {
        int row = tid >> 2;
        int ec  = (tid & 3) * 32;
        int node = node0 + row;
        if (node < NN) {
            if (ec < OC) {
                float* tp = g_t + (size_t)node * OC + ec;
                float* zp = g_aggF + (size_t)node * OC + ec;
#pragma unroll
                for (int q = 0; q < 8; q++) {
                    *reinterpret_cast<float4*>(tp + q * 4) =
                        *reinterpret_cast<const float4*>(Df + row * FLD + ec + q * 4);
                    *reinterpret_cast<float4*>(zp + q * 4) =
                        make_float4(0.f, 0.f, 0.f, 0.f);
                }
            } else {
                float* pp = g_po + (size_t)node * OC + (ec - OC);
                float* zp = g_aggF + (size_t)node * OC + (ec - OC);
#pragma unroll
                for (int q = 0; q < 8; q++) {
                    *reinterpret_cast<float4*>(pp + q * 4) =
                        *reinterpret_cast<const float4*>(Df + row * FLD + ec + q * 4);
                    *reinterpret_cast<float4*>(zp + q * 4) =
                        make_float4(0.f, 0.f, 0.f, 0.f);
                }
            }
        }
    }
}

// ---------------- kernel 4: scatter t, 4 edges per half-warp (R6 config) ----
__global__ void k_scatter_t(const int* __restrict__ ei) {
    int hw = (blockIdx.x * blockDim.x + threadIdx.x) >> 4;
    int lane = threadIdx.x & 15;
    int e0 = hw * 4;
    if (e0 >= NE) return;
    int s[4], d[4];
    bool ok[4];
#pragma unroll
    for (int e = 0; e < 4; e++) {
        s[e] = ei[e0 + e];
        d[e] = ei[NE + e0 + e];
        ok[e] = ((unsigned)s[e] < NN) && ((unsigned)d[e] < NN);
    }
    float4 v[4];
#pragma unroll
    for (int e = 0; e < 4; e++)
        if (ok[e])
            v[e] = *reinterpret_cast<const float4*>(g_t + (size_t)s[e] * OC + lane * 4);
#pragma unroll
    for (int e = 0; e < 4; e++)
        if (ok[e])
            red_add_v4(g_aggF + (size_t)d[e] * OC + lane * 4, v[e]);
}

// ---------------- kernel 5: out = aggF / max(cnt0,1) + po -------------------
__global__ void k_final(float* __restrict__ out) {
    int i = blockIdx.x * blockDim.x + threadIdx.x;
    int stride = gridDim.x * blockDim.x;
    int n4 = NN * OC / 4;
    const float4* a4 = reinterpret_cast<const float4*>(g_aggF);
    const float4* p4 = reinterpret_cast<const float4*>(g_po);
    float4* o4 = reinterpret_cast<float4*>(out);
    for (int j = i; j < n4; j += stride) {
        int node = j / (OC / 4);
        float inv = 1.f / fmaxf(g_cnt[node], 1.f);
        float4 a = a4[j];
        float4 p = p4[j];
        o4[j] = make_float4(a.x * inv + p.x, a.y * inv + p.y,
                            a.z * inv + p.z, a.w * inv + p.w);
    }
}

// ---------------- launch ----------------------------------------------------
extern "C" void kernel_launch(void* const* d_in, const int* in_sizes, int n_in,
                              void* d_out, int out_size) {
    const float* x   = (const float*)d_in[0];
    const float* Wl  = (const float*)d_in[1];
    const float* bl  = (const float*)d_in[2];
    const float* Wr  = (const float*)d_in[3];
    const float* Wlf = (const float*)d_in[4];
    const float* blf = (const float*)d_in[5];
    const float* Wrf = (const float*)d_in[6];
    const int* ei0   = (const int*)d_in[7];
    const int* ei1   = (const int*)d_in[8];
    const int* ei2   = (const int*)d_in[9];
    float* out = (float*)d_out;

    void *pagg, *pcnt;
    cudaGetSymbolAddress(&pagg, g_agg);
    cudaGetSymbolAddress(&pcnt, g_cnt);
    cudaMemsetAsync(pagg, 0, (size_t)NREL * NN * C * sizeof(float), 0);
    cudaMemsetAsync(pcnt, 0, (size_t)NREL * NN * sizeof(float), 0);

    k_prep<<<1, 256>>>(bl, blf);

    // 4 edges per warp, 8 warps per 256-thr block, y = relation (R6 config)
    dim3 sgrid((NE / 4 + 7) / 8, 3);
    k_scatter_x<<<sgrid, 256>>>(x, ei0, ei1, ei2);

    const int SMEMF = 4 * 128 * HLD * 2;  // 139264
    cudaFuncSetAttribute(k_gemm_fused, cudaFuncAttributeMaxDynamicSharedMemorySize, SMEMF);
    int gb = (NN + 127) / 128;  // 782
    k_gemm_fused<<<gb, 512, SMEMF>>>(x, Wl, Wr, Wlf, Wrf);

    // 4 edges per half-warp, 16 half-warps per 256-thr block (R6 config)
    k_scatter_t<<<(NE / 4 + 15) / 16, 256>>>(ei0);
    k_final<<<2048, 256>>>(out);
}